// round 3
// baseline (speedup 1.0000x reference)
#include <cuda_runtime.h>
#include <cuda_bf16.h>
#include <math.h>

// Problem constants
#define BB    16      // batch
#define DIM   256
#define S     64      // channels per branch
#define NPOS  4096    // H*W = 64*64
#define HEADS 4
#define HD    16

// ------------------------- scratch (static device memory) -------------------------
// layouts: g_A[br][b][c][n]; g_q/k/v[br][b][h][n][d]; ctx/stats per (br*64 + b*4 + h)
__device__ float g_A[4 * BB * S * NPOS];
__device__ float g_q[4 * BB * HEADS * NPOS * HD];
__device__ float g_k[4 * BB * HEADS * NPOS * HD];
__device__ float g_v[4 * BB * HEADS * NPOS * HD];
__device__ float g_ctx[4 * BB * HEADS * HD * HD];
__device__ float g_colmax[4 * BB * HEADS * HD];
__device__ float g_colsum[4 * BB * HEADS * HD];
__device__ float g_cat[BB * NPOS * DIM];   // reference-scrambled layout (b, n', c')
__device__ float g_M[DIM * DIM];           // fused proj*final weight
__device__ float g_c0[DIM];                // fused bias

// ------------------------- K0: fuse proj + final conv weights -------------------------
// M[co][i*64+c'] = scale_i * sum_j Wf[co][i*64+j] * Wp[j][c']
// c0[co] = b_final[co] + sum_i scale_i * sum_j Wf[co][i*64+j] * b_proj[j]
__global__ void __launch_bounds__(256) k0_fuse(
        const float* __restrict__ wf, const float* __restrict__ wp,
        const float* __restrict__ bp, const float* __restrict__ bf,
        const float* __restrict__ sw) {
    int co = blockIdx.x;
    int t = threadIdx.x;           // 256 threads: one M entry each
    int i = t >> 6;                // branch
    int cp = t & 63;               // attention-output channel c'
    float s = 0.f;
    const float* wfr = wf + co * DIM + i * S;
    #pragma unroll 8
    for (int j = 0; j < S; ++j) s += wfr[j] * wp[j * S + cp];
    g_M[co * DIM + t] = s * sw[i];
    if (t == 0) {
        float cc = bf[co];
        for (int i2 = 0; i2 < 4; ++i2) {
            float ss = 0.f;
            const float* wfr2 = wf + co * DIM + i2 * S;
            for (int j = 0; j < S; ++j) ss += wfr2[j] * bp[j];
            cc += sw[i2] * ss;
        }
        g_c0[co] = cc;
    }
}

// ------------------------- K1: depthwise conv + bias + residual + relu -------------------------
template <int K>
__device__ __forceinline__ void dwconv_body(const float* __restrict__ x,
                                            const float* __restrict__ w,
                                            const float* __restrict__ bias,
                                            int br, float* sm, float* wsm) {
    const int c = blockIdx.x;      // 0..63
    const int b = blockIdx.y;      // 0..15
    const int t = threadIdx.x;     // 256

    const float* xp = x + ((size_t)(b * DIM + br * S + c)) * NPOS;

    for (int l = t; l < 72 * 72; l += 256) sm[l] = 0.f;
    if (t < K * K) wsm[t] = w[c * K * K + t];
    __syncthreads();
    for (int l = t; l < NPOS; l += 256) {
        int h = l >> 6, wd = l & 63;
        sm[(h + 4) * 72 + wd + 4] = xp[l];
    }
    __syncthreads();

    const int pad = K / 2;
    const float bc = bias[c];
    float* dst = g_A + ((size_t)((br * BB + b) * S + c)) * NPOS;
    for (int l = t; l < NPOS; l += 256) {
        int h = l >> 6, wd = l & 63;
        float s = 0.f;
        #pragma unroll
        for (int ky = 0; ky < K; ++ky) {
            #pragma unroll
            for (int kx = 0; kx < K; ++kx) {
                s += sm[(h + 4 + ky - pad) * 72 + (wd + 4 + kx - pad)] * wsm[ky * K + kx];
            }
        }
        float r = s + bc + sm[(h + 4) * 72 + wd + 4];
        dst[l] = r > 0.f ? r : 0.f;
    }
}

__global__ void __launch_bounds__(256) k1_dwconv_all(
        const float* __restrict__ x,
        const float* __restrict__ w3, const float* __restrict__ b3,
        const float* __restrict__ w5, const float* __restrict__ b5,
        const float* __restrict__ w7, const float* __restrict__ b7,
        const float* __restrict__ w9, const float* __restrict__ b9) {
    __shared__ float sm[72 * 72];
    __shared__ float wsm[81];
    switch (blockIdx.z) {
        case 0: dwconv_body<3>(x, w3, b3, 0, sm, wsm); break;
        case 1: dwconv_body<5>(x, w5, b5, 1, sm, wsm); break;
        case 2: dwconv_body<7>(x, w7, b7, 2, sm, wsm); break;
        default: dwconv_body<9>(x, w9, b9, 3, sm, wsm); break;
    }
}

// ------------------------- K2: QKV GEMM (3 x 64x64 out tiles, K=64) -------------------------
__global__ void __launch_bounds__(256) k2_qkv(const float* __restrict__ wqkv) {
    const int br = blockIdx.z;
    const int b = blockIdx.y;
    const int n0 = blockIdx.x * 64;
    const int t = threadIdx.x;
    const int tx = t & 15, ty = t >> 4;

    __shared__ float ws[64 * 68];  // weights transposed; reused as output stage (stride 65)
    __shared__ float xt[64 * 68];  // xt[c*68 + j]

    for (int l = t; l < 4096; l += 256) {
        int c = l >> 6, j = l & 63;
        xt[c * 68 + j] = g_A[((size_t)((br * BB + b) * S + c)) * NPOS + n0 + j];
    }

    for (int pass = 0; pass < 3; ++pass) {
        __syncthreads();
        for (int l = t; l < 4096; l += 256) {
            int r = l >> 6, kk = l & 63;
            ws[kk * 68 + r] = wqkv[(pass * 64 + r) * 64 + kk];
        }
        __syncthreads();

        float acc[4][4];
        #pragma unroll
        for (int j = 0; j < 4; ++j)
            #pragma unroll
            for (int i = 0; i < 4; ++i) acc[j][i] = 0.f;

        #pragma unroll 4
        for (int kk = 0; kk < 64; ++kk) {
            float4 a = *(const float4*)&xt[kk * 68 + tx * 4];
            float4 wv = *(const float4*)&ws[kk * 68 + ty * 4];
            acc[0][0] += wv.x * a.x; acc[0][1] += wv.x * a.y; acc[0][2] += wv.x * a.z; acc[0][3] += wv.x * a.w;
            acc[1][0] += wv.y * a.x; acc[1][1] += wv.y * a.y; acc[1][2] += wv.y * a.z; acc[1][3] += wv.y * a.w;
            acc[2][0] += wv.z * a.x; acc[2][1] += wv.z * a.y; acc[2][2] += wv.z * a.z; acc[2][3] += wv.z * a.w;
            acc[3][0] += wv.w * a.x; acc[3][1] += wv.w * a.y; acc[3][2] += wv.w * a.z; acc[3][3] += wv.w * a.w;
        }
        __syncthreads();
        #pragma unroll
        for (int j = 0; j < 4; ++j)
            #pragma unroll
            for (int i = 0; i < 4; ++i)
                ws[(ty * 4 + j) * 65 + tx * 4 + i] = acc[j][i];
        __syncthreads();

        float* dst = (pass == 0) ? g_q : (pass == 1) ? g_k : g_v;
        for (int l = t; l < 4096; l += 256) {
            int h = l >> 10;
            int p = (l >> 4) & 63;
            int d = l & 15;
            dst[((size_t)((br * BB + b) * HEADS + h)) * (NPOS * HD) + (size_t)n0 * HD + (l & 1023)] =
                ws[(h * 16 + d) * 65 + p];
        }
    }
}

// ------------------------- K3: context (key softmax over d) + q column stats over n ----------
__global__ void __launch_bounds__(256) k3_ctx() {
    const int gbh = blockIdx.y * (BB * HEADS) + blockIdx.x;  // br*64 + b*4 + h
    const int t = threadIdx.x;     // 256
    const int d = t >> 4, e = t & 15;
    __shared__ float ks[64 * 16];
    __shared__ float vs[64 * 16];

    const size_t base0 = (size_t)gbh * (NPOS * HD);
    float acc = 0.f;
    for (int tile = 0; tile < 64; ++tile) {
        const size_t base = base0 + (size_t)tile * 1024;
        for (int l = t; l < 1024; l += 256) {
            ks[l] = g_k[base + l];
            vs[l] = g_v[base + l];
        }
        __syncthreads();
        if (t < 64) {
            float m = -1e30f;
            #pragma unroll
            for (int dd = 0; dd < 16; ++dd) m = fmaxf(m, ks[t * 16 + dd]);
            float s = 0.f;
            #pragma unroll
            for (int dd = 0; dd < 16; ++dd) {
                float ex = __expf(ks[t * 16 + dd] - m);
                ks[t * 16 + dd] = ex;
                s += ex;
            }
            float inv = 1.f / s;
            #pragma unroll
            for (int dd = 0; dd < 16; ++dd) ks[t * 16 + dd] *= inv;
        }
        __syncthreads();
        #pragma unroll 8
        for (int p = 0; p < 64; ++p) acc += ks[p * 16 + d] * vs[p * 16 + e];
        __syncthreads();
    }
    g_ctx[gbh * 256 + d * 16 + e] = acc;

    // --- phase B: per-d online max/sumexp over all n (for softmax over axis n) ---
    float m = -1e30f, s = 0.f;
    for (int j = 0; j < 256; ++j) {
        float v = g_q[base0 + (size_t)j * 256 + t];
        if (v > m) {
            s = s * __expf(m - v) + 1.f;
            m = v;
        } else {
            s += __expf(v - m);
        }
    }
    __syncthreads();               // ks/vs reuse
    ks[(t >> 4) * 16 + (t & 15)] = m;
    vs[(t >> 4) * 16 + (t & 15)] = s;
    __syncthreads();
    if (t < 16) {
        float M = -1e30f;
        for (int p = 0; p < 16; ++p) M = fmaxf(M, ks[p * 16 + t]);
        float Ssum = 0.f;
        for (int p = 0; p < 16; ++p) Ssum += vs[p * 16 + t] * __expf(ks[p * 16 + t] - M);
        g_colmax[gbh * 16 + t] = M;
        g_colsum[gbh * 16 + t] = Ssum;
    }
}

// ------------------------- K4: attention output -> cat buffer (reference reshape layout) ------
// A[b,h,nn,e] lands at cat[b, h*1024 + nn/4, br*64 + (nn%4)*16 + e]
__global__ void __launch_bounds__(256) k4_attn() {
    const int br = blockIdx.z;
    const int b = blockIdx.y;
    const int n0 = blockIdx.x * 64;
    const int t = threadIdx.x;
    __shared__ float qs[4 * 64 * 17];
    __shared__ float ctxs[4 * 256];
    __shared__ float cexp[64];     // cms + log(colsum) folded into one constant per (h,d)

    const int gb = (br * BB + b) * HEADS;   // (br,b) head base
    for (int l = t; l < 1024; l += 256) ctxs[l] = g_ctx[gb * 256 + l];
    if (t < 64) {
        cexp[t] = g_colmax[gb * 16 + t] + __logf(g_colsum[gb * 16 + t]);
    }
    for (int l = t; l < 4096; l += 256) {
        int h = l >> 10;
        int p = (l >> 4) & 63;
        int dd = l & 15;
        qs[h * 1088 + p * 17 + dd] =
            g_q[((size_t)(gb + h)) * (NPOS * HD) + (size_t)n0 * HD + (l & 1023)];
    }
    __syncthreads();

    const int p = t & 63, h = t >> 6;
    float acc[16];
    #pragma unroll
    for (int e = 0; e < 16; ++e) acc[e] = 0.f;
    #pragma unroll
    for (int dd = 0; dd < 16; ++dd) {
        float qv = __expf(qs[h * 1088 + p * 17 + dd] - cexp[h * 16 + dd]);
        #pragma unroll
        for (int e = 0; e < 16; ++e) acc[e] += qv * ctxs[h * 256 + dd * 16 + e];
    }
    const int nn = n0 + p;
    const int npr = h * 1024 + (nn >> 2);          // scrambled position
    const int cpb = (nn & 3) * 16;                 // scrambled channel base within branch
    float* dst = g_cat + ((size_t)(b * NPOS + npr)) * DIM + br * S + cpb;
    #pragma unroll
    for (int e4 = 0; e4 < 4; ++e4) {
        float4 v = make_float4(acc[e4 * 4 + 0], acc[e4 * 4 + 1], acc[e4 * 4 + 2], acc[e4 * 4 + 3]);
        *(float4*)&dst[e4 * 4] = v;
    }
}

// ------------------------- K5: fused final GEMM: out = M @ cat^T + c0 -------------------------
__global__ void __launch_bounds__(256) k5_final(float* __restrict__ out) {
    const int b = blockIdx.z;
    const int co0 = blockIdx.y * 64;
    const int n0 = blockIdx.x * 64;
    const int t = threadIdx.x;
    const int tx = t & 15, ty = t >> 4;

    __shared__ float cs[64 * 68];   // cs[kk*68 + p]
    __shared__ float wfs[64 * 68];  // wfs[kk*68 + co]

    float acc[4][4];
    #pragma unroll
    for (int j = 0; j < 4; ++j)
        #pragma unroll
        for (int i = 0; i < 4; ++i) acc[j][i] = 0.f;

    for (int chunk = 0; chunk < 4; ++chunk) {
        const int ci0 = chunk * 64;
        __syncthreads();
        for (int l = t; l < 4096; l += 256) {
            int p = l >> 6, kk = l & 63;
            cs[kk * 68 + p] = g_cat[((size_t)(b * NPOS + n0 + p)) * DIM + ci0 + kk];
        }
        for (int l = t; l < 4096; l += 256) {
            int co = l >> 6, kk = l & 63;
            wfs[kk * 68 + co] = g_M[(co0 + co) * DIM + ci0 + kk];
        }
        __syncthreads();
        #pragma unroll 4
        for (int kk = 0; kk < 64; ++kk) {
            float4 a = *(const float4*)&cs[kk * 68 + tx * 4];
            float4 wv = *(const float4*)&wfs[kk * 68 + ty * 4];
            acc[0][0] += wv.x * a.x; acc[0][1] += wv.x * a.y; acc[0][2] += wv.x * a.z; acc[0][3] += wv.x * a.w;
            acc[1][0] += wv.y * a.x; acc[1][1] += wv.y * a.y; acc[1][2] += wv.y * a.z; acc[1][3] += wv.y * a.w;
            acc[2][0] += wv.z * a.x; acc[2][1] += wv.z * a.y; acc[2][2] += wv.z * a.z; acc[2][3] += wv.z * a.w;
            acc[3][0] += wv.w * a.x; acc[3][1] += wv.w * a.y; acc[3][2] += wv.w * a.z; acc[3][3] += wv.w * a.w;
        }
    }

    #pragma unroll
    for (int j = 0; j < 4; ++j) {
        int co = co0 + ty * 4 + j;
        float cc = g_c0[co];
        float4 v = make_float4(acc[j][0] + cc, acc[j][1] + cc, acc[j][2] + cc, acc[j][3] + cc);
        *(float4*)&out[((size_t)(b * DIM + co)) * NPOS + n0 + tx * 4] = v;
    }
}

// ------------------------- launch -------------------------
extern "C" void kernel_launch(void* const* d_in, const int* in_sizes, int n_in,
                              void* d_out, int out_size) {
    const float* x      = (const float*)d_in[0];
    const float* w3 = (const float*)d_in[1];  const float* b3 = (const float*)d_in[2];
    const float* w5 = (const float*)d_in[3];  const float* b5 = (const float*)d_in[4];
    const float* w7 = (const float*)d_in[5];  const float* b7 = (const float*)d_in[6];
    const float* w9 = (const float*)d_in[7];  const float* b9 = (const float*)d_in[8];
    const float* w_qkv  = (const float*)d_in[9];
    const float* w_proj = (const float*)d_in[10];
    const float* b_proj = (const float*)d_in[11];
    const float* w_fin  = (const float*)d_in[12];
    const float* b_fin  = (const float*)d_in[13];
    const float* sw     = (const float*)d_in[14];
    float* out = (float*)d_out;

    k0_fuse<<<DIM, 256>>>(w_fin, w_proj, b_proj, b_fin, sw);
    k1_dwconv_all<<<dim3(S, BB, 4), 256>>>(x, w3, b3, w5, b5, w7, b7, w9, b9);
    k2_qkv<<<dim3(64, BB, 4), 256>>>(w_qkv);
    k3_ctx<<<dim3(BB * HEADS, 4), 256>>>();
    k4_attn<<<dim3(64, BB, 4), 256>>>();
    k5_final<<<dim3(64, 4, BB), 256>>>(out);
}

// round 7
// speedup vs baseline: 1.6955x; 1.6955x over previous
#include <cuda_runtime.h>
#include <cuda_bf16.h>
#include <math.h>

#define BB    16
#define DIM   256
#define S     64
#define NPOS  4096
#define HEADS 4
#define HD    16

// ------------------------- scratch -------------------------
__device__ float g_A[4 * BB * S * NPOS];        // [br][b][c][n]
__device__ float g_q[4 * BB * HEADS * NPOS * HD];
__device__ float g_pctx[4 * BB * HEADS * 64 * 256];  // per-tile partial ctx
__device__ float g_qm[4 * BB * 64 * 64];        // per-tile q col max  [col][tile]
__device__ float g_qs[4 * BB * 64 * 64];        // per-tile q col sumexp
__device__ float g_ctx[4 * BB * HEADS * HD * HD];
__device__ float g_colmax[4 * BB * HEADS * HD];
__device__ float g_colsum[4 * BB * HEADS * HD];
__device__ float g_cat[BB * NPOS * DIM];        // scrambled (b, n', c')
__device__ float g_M[DIM * DIM];
__device__ float g_c0[DIM];

// ------------------------- K0: fuse proj + final weights -------------------------
__global__ void __launch_bounds__(256) k0_fuse(
        const float* __restrict__ wf, const float* __restrict__ wp,
        const float* __restrict__ bp, const float* __restrict__ bf,
        const float* __restrict__ sw) {
    int co = blockIdx.x;
    int t = threadIdx.x;
    int i = t >> 6;
    int cp = t & 63;
    float s = 0.f;
    const float* wfr = wf + co * DIM + i * S;
    #pragma unroll 8
    for (int j = 0; j < S; ++j) s += wfr[j] * wp[j * S + cp];
    g_M[co * DIM + t] = s * sw[i];
    if (t == 0) {
        float cc = bf[co];
        for (int i2 = 0; i2 < 4; ++i2) {
            float ss = 0.f;
            const float* wfr2 = wf + co * DIM + i2 * S;
            for (int j = 0; j < S; ++j) ss += wfr2[j] * bp[j];
            cc += sw[i2] * ss;
        }
        g_c0[co] = cc;
    }
}

// ------------------------- K1: depthwise conv, 4 outputs/thread -------------------------
template <int K>
__device__ __forceinline__ void dwconv_body(const float* __restrict__ x,
                                            const float* __restrict__ w,
                                            const float* __restrict__ bias,
                                            int br, float* sm, float* wsm) {
    const int c = blockIdx.x;
    const int b = blockIdx.y;
    const int t = threadIdx.x;
    const int pad = K / 2;

    const float* xp = x + ((size_t)(b * DIM + br * S + c)) * NPOS;

    for (int l = t; l < 72 * 72; l += 256) sm[l] = 0.f;
    if (t < K * K) wsm[t] = w[c * K * K + t];
    __syncthreads();
    #pragma unroll
    for (int pass = 0; pass < 4; ++pass) {
        int quad = pass * 1024 + t * 4;
        int h = quad >> 6, wd = quad & 63;
        float4 v = *(const float4*)&xp[quad];
        *(float4*)&sm[(h + 4) * 72 + wd + 4] = v;
    }
    __syncthreads();

    const float bc = bias[c];
    float* dst = g_A + ((size_t)((br * BB + b) * S + c)) * NPOS;
    #pragma unroll
    for (int pass = 0; pass < 4; ++pass) {
        int quad = pass * 1024 + t * 4;
        int h = quad >> 6, x0 = quad & 63;
        float acc0 = 0.f, acc1 = 0.f, acc2 = 0.f, acc3 = 0.f;
        #pragma unroll
        for (int ky = 0; ky < K; ++ky) {
            const float* row = &sm[(h + 4 + ky - pad) * 72 + x0];
            float4 r0 = *(const float4*)&row[0];
            float4 r1 = *(const float4*)&row[4];
            float4 r2 = *(const float4*)&row[8];
            float rv[12] = {r0.x, r0.y, r0.z, r0.w, r1.x, r1.y, r1.z, r1.w,
                            r2.x, r2.y, r2.z, r2.w};
            #pragma unroll
            for (int kx = 0; kx < K; ++kx) {
                float wv = wsm[ky * K + kx];
                int o = 4 - pad + kx;
                acc0 += rv[o + 0] * wv;
                acc1 += rv[o + 1] * wv;
                acc2 += rv[o + 2] * wv;
                acc3 += rv[o + 3] * wv;
            }
        }
        float4 cen = *(const float4*)&sm[(h + 4) * 72 + x0 + 4];
        float4 o;
        o.x = fmaxf(acc0 + bc + cen.x, 0.f);
        o.y = fmaxf(acc1 + bc + cen.y, 0.f);
        o.z = fmaxf(acc2 + bc + cen.z, 0.f);
        o.w = fmaxf(acc3 + bc + cen.w, 0.f);
        *(float4*)&dst[h * 64 + x0] = o;
    }
}

__global__ void __launch_bounds__(256) k1_dwconv_all(
        const float* __restrict__ x,
        const float* __restrict__ w3, const float* __restrict__ b3,
        const float* __restrict__ w5, const float* __restrict__ b5,
        const float* __restrict__ w7, const float* __restrict__ b7,
        const float* __restrict__ w9, const float* __restrict__ b9) {
    __shared__ __align__(16) float sm[72 * 72];
    __shared__ float wsm[81];
    switch (blockIdx.z) {
        case 0: dwconv_body<3>(x, w3, b3, 0, sm, wsm); break;
        case 1: dwconv_body<5>(x, w5, b5, 1, sm, wsm); break;
        case 2: dwconv_body<7>(x, w7, b7, 2, sm, wsm); break;
        default: dwconv_body<9>(x, w9, b9, 3, sm, wsm); break;
    }
}

// ------------------------- K2: fused QKV GEMM + key-softmax ctx partial + q stats ----------
__global__ void __launch_bounds__(256) k2_qkv(const float* __restrict__ wqkv) {
    const int tile = blockIdx.x;          // 0..63
    const int b = blockIdx.y;
    const int br = blockIdx.z;
    const int n0 = tile * 64;
    const int t = threadIdx.x;
    const int tx = t & 15, ty = t >> 4;

    __shared__ __align__(16) float xt[64 * 68];        // activations [c][j]; later k-stage [r*65+p]
    __shared__ __align__(16) float ws3[3 * 32 * 68];   // weights [pass][kk][r]; later q/v stage
    __shared__ float srm[256], srs[256];

    for (int l = t; l < 1024; l += 256) {
        int c = l >> 4, j4 = (l & 15) * 4;
        float4 v = *(const float4*)&g_A[((size_t)((br * BB + b) * S + c)) * NPOS + n0 + j4];
        *(float4*)&xt[c * 68 + j4] = v;
    }

    float aQ[4][4], aK[4][4], aV[4][4];
    #pragma unroll
    for (int j = 0; j < 4; ++j)
        #pragma unroll
        for (int i = 0; i < 4; ++i) { aQ[j][i] = 0.f; aK[j][i] = 0.f; aV[j][i] = 0.f; }

    for (int chunk = 0; chunk < 2; ++chunk) {
        const int c0 = chunk * 32;
        __syncthreads();
        for (int l = t; l < 1536; l += 256) {
            int pp = l / 512;
            int rem = l & 511;
            int r = rem >> 3, kk4 = (rem & 7) * 4;
            float4 v = *(const float4*)&wqkv[(pp * 64 + r) * 64 + c0 + kk4];
            float* dst = &ws3[pp * 2176 + kk4 * 68 + r];
            dst[0] = v.x; dst[68] = v.y; dst[136] = v.z; dst[204] = v.w;
        }
        __syncthreads();
        #pragma unroll 4
        for (int kk = 0; kk < 32; ++kk) {
            float4 a = *(const float4*)&xt[(c0 + kk) * 68 + tx * 4];
            float4 wq = *(const float4*)&ws3[kk * 68 + ty * 4];
            float4 wk = *(const float4*)&ws3[2176 + kk * 68 + ty * 4];
            float4 wv = *(const float4*)&ws3[4352 + kk * 68 + ty * 4];
            aQ[0][0] += wq.x * a.x; aQ[0][1] += wq.x * a.y; aQ[0][2] += wq.x * a.z; aQ[0][3] += wq.x * a.w;
            aQ[1][0] += wq.y * a.x; aQ[1][1] += wq.y * a.y; aQ[1][2] += wq.y * a.z; aQ[1][3] += wq.y * a.w;
            aQ[2][0] += wq.z * a.x; aQ[2][1] += wq.z * a.y; aQ[2][2] += wq.z * a.z; aQ[2][3] += wq.z * a.w;
            aQ[3][0] += wq.w * a.x; aQ[3][1] += wq.w * a.y; aQ[3][2] += wq.w * a.z; aQ[3][3] += wq.w * a.w;
            aK[0][0] += wk.x * a.x; aK[0][1] += wk.x * a.y; aK[0][2] += wk.x * a.z; aK[0][3] += wk.x * a.w;
            aK[1][0] += wk.y * a.x; aK[1][1] += wk.y * a.y; aK[1][2] += wk.y * a.z; aK[1][3] += wk.y * a.w;
            aK[2][0] += wk.z * a.x; aK[2][1] += wk.z * a.y; aK[2][2] += wk.z * a.z; aK[2][3] += wk.z * a.w;
            aK[3][0] += wk.w * a.x; aK[3][1] += wk.w * a.y; aK[3][2] += wk.w * a.z; aK[3][3] += wk.w * a.w;
            aV[0][0] += wv.x * a.x; aV[0][1] += wv.x * a.y; aV[0][2] += wv.x * a.z; aV[0][3] += wv.x * a.w;
            aV[1][0] += wv.y * a.x; aV[1][1] += wv.y * a.y; aV[1][2] += wv.y * a.z; aV[1][3] += wv.y * a.w;
            aV[2][0] += wv.z * a.x; aV[2][1] += wv.z * a.y; aV[2][2] += wv.z * a.z; aV[2][3] += wv.z * a.w;
            aV[3][0] += wv.w * a.x; aV[3][1] += wv.w * a.y; aV[3][2] += wv.w * a.z; aV[3][3] += wv.w * a.w;
        }
    }
    __syncthreads();

    // stage q -> ws3 region [r*65+p], k -> xt region [r*65+p]
    #pragma unroll
    for (int j = 0; j < 4; ++j)
        #pragma unroll
        for (int i = 0; i < 4; ++i) {
            ws3[(ty * 4 + j) * 65 + tx * 4 + i] = aQ[j][i];
            xt[(ty * 4 + j) * 65 + tx * 4 + i] = aK[j][i];
        }
    __syncthreads();

    // q output (layout (b,h,n,d))
    const int gb = (br * BB + b) * HEADS;
    for (int l = t; l < 4096; l += 256) {
        int h = l >> 10;
        int p = (l >> 4) & 63;
        int d = l & 15;
        g_q[((size_t)(gb + h)) * (NPOS * HD) + (size_t)n0 * HD + (l & 1023)] =
            ws3[(h * 16 + d) * 65 + p];
    }
    // q per-tile column stats: (r, quarter) scans 16 positions
    {
        int r = t & 63, qtr = t >> 6;
        float m = -1e30f;
        #pragma unroll
        for (int i = 0; i < 16; ++i) m = fmaxf(m, ws3[r * 65 + qtr * 16 + i]);
        float s = 0.f;
        #pragma unroll
        for (int i = 0; i < 16; ++i) s += __expf(ws3[r * 65 + qtr * 16 + i] - m);
        srm[t] = m;
        srs[t] = s;
    }
    __syncthreads();
    if (t < 64) {
        float M = srm[t];
        M = fmaxf(M, srm[64 + t]);
        M = fmaxf(M, srm[128 + t]);
        M = fmaxf(M, srm[192 + t]);
        float Ssum = srs[t] * __expf(srm[t] - M)
                   + srs[64 + t] * __expf(srm[64 + t] - M)
                   + srs[128 + t] * __expf(srm[128 + t] - M)
                   + srs[192 + t] * __expf(srm[192 + t] - M);
        int col = (br * BB + b) * 64 + t;
        g_qm[col * 64 + tile] = M;
        g_qs[col * 64 + tile] = Ssum;
    }
    __syncthreads();

    // stage v transposed -> ws3 region [p*68 + r]
    #pragma unroll
    for (int j = 0; j < 4; ++j)
        #pragma unroll
        for (int i = 0; i < 4; ++i)
            ws3[(tx * 4 + i) * 68 + ty * 4 + j] = aV[j][i];
    __syncthreads();

    // key softmax over d (per h, position)
    {
        int h = t >> 6, p = t & 63;
        float m = -1e30f;
        #pragma unroll
        for (int d = 0; d < 16; ++d) m = fmaxf(m, xt[(h * 16 + d) * 65 + p]);
        float s = 0.f;
        float ex[16];
        #pragma unroll
        for (int d = 0; d < 16; ++d) {
            ex[d] = __expf(xt[(h * 16 + d) * 65 + p] - m);
            s += ex[d];
        }
        float inv = 1.f / s;
        #pragma unroll
        for (int d = 0; d < 16; ++d) xt[(h * 16 + d) * 65 + p] = ex[d] * inv;
    }
    __syncthreads();

    // partial ctx[h][d][e] = sum_p khat[d,p] * v[e,p]
    {
        int h = t >> 6, d = (t >> 2) & 15, eq = t & 3;
        float4 acc = make_float4(0.f, 0.f, 0.f, 0.f);
        #pragma unroll 8
        for (int p = 0; p < 64; ++p) {
            float kd = xt[(h * 16 + d) * 65 + p];
            float4 v4 = *(const float4*)&ws3[p * 68 + h * 16 + eq * 4];
            acc.x += kd * v4.x; acc.y += kd * v4.y; acc.z += kd * v4.z; acc.w += kd * v4.w;
        }
        *(float4*)&g_pctx[(((size_t)(gb + h)) * 64 + tile) * 256 + d * 16 + eq * 4] = acc;
    }
}

// ------------------------- K3r: reduce partial ctx + q stats -------------------------
__global__ void __launch_bounds__(256) k3r_reduce() {
    const int gbh = blockIdx.x;   // 0..255
    const int t = threadIdx.x;
    float acc = 0.f;
    const float* src = g_pctx + (size_t)gbh * 64 * 256 + t;
    #pragma unroll 8
    for (int tile = 0; tile < 64; ++tile) acc += src[tile * 256];
    g_ctx[gbh * 256 + t] = acc;

    if (t < 16) {
        int col = gbh * 16 + t;
        const float* pm = g_qm + col * 64;
        const float* ps = g_qs + col * 64;
        float M = -1e30f;
        #pragma unroll 8
        for (int tile = 0; tile < 64; ++tile) M = fmaxf(M, pm[tile]);
        float Ssum = 0.f;
        #pragma unroll 8
        for (int tile = 0; tile < 64; ++tile) Ssum += ps[tile] * __expf(pm[tile] - M);
        g_colmax[col] = M;
        g_colsum[col] = Ssum;
    }
}

// ------------------------- K4: attention output -> cat (scrambled reshape) -------------------
__global__ void __launch_bounds__(256) k4_attn() {
    const int br = blockIdx.z;
    const int b = blockIdx.y;
    const int n0 = blockIdx.x * 64;
    const int t = threadIdx.x;
    __shared__ float qs[4 * 64 * 17];
    __shared__ float ctxs[4 * 256];
    __shared__ float cexp[64];

    const int gb = (br * BB + b) * HEADS;
    for (int l = t; l < 1024; l += 256) ctxs[l] = g_ctx[gb * 256 + l];
    if (t < 64) {
        cexp[t] = g_colmax[gb * 16 + t] + __logf(g_colsum[gb * 16 + t]);
    }
    for (int l = t; l < 4096; l += 256) {
        int h = l >> 10;
        int p = (l >> 4) & 63;
        int dd = l & 15;
        qs[h * 1088 + p * 17 + dd] =
            g_q[((size_t)(gb + h)) * (NPOS * HD) + (size_t)n0 * HD + (l & 1023)];
    }
    __syncthreads();

    const int p = t & 63, h = t >> 6;
    float acc[16];
    #pragma unroll
    for (int e = 0; e < 16; ++e) acc[e] = 0.f;
    #pragma unroll
    for (int dd = 0; dd < 16; ++dd) {
        float qv = __expf(qs[h * 1088 + p * 17 + dd] - cexp[h * 16 + dd]);
        #pragma unroll
        for (int e = 0; e < 16; ++e) acc[e] += qv * ctxs[h * 256 + dd * 16 + e];
    }
    const int nn = n0 + p;
    const int npr = h * 1024 + (nn >> 2);
    const int cpb = (nn & 3) * 16;
    float* dst = g_cat + ((size_t)(b * NPOS + npr)) * DIM + br * S + cpb;
    #pragma unroll
    for (int e4 = 0; e4 < 4; ++e4) {
        float4 v = make_float4(acc[e4 * 4 + 0], acc[e4 * 4 + 1], acc[e4 * 4 + 2], acc[e4 * 4 + 3]);
        *(float4*)&dst[e4 * 4] = v;
    }
}

// ------------------------- K5: final GEMM 128x128 tile, 8x8 micro -------------------------
__global__ void __launch_bounds__(256) k5_final(float* __restrict__ out) {
    const int n0 = blockIdx.x * 128;
    const int co0 = blockIdx.y * 128;
    const int b = blockIdx.z;
    const int t = threadIdx.x;
    const int tx = t & 15, ty = t >> 4;

    __shared__ __align__(16) float cs[32 * 132];
    __shared__ __align__(16) float wfs[32 * 132];

    float acc[8][8];
    #pragma unroll
    for (int j = 0; j < 8; ++j)
        #pragma unroll
        for (int i = 0; i < 8; ++i) acc[j][i] = 0.f;

    for (int chunk = 0; chunk < 8; ++chunk) {
        const int ci0 = chunk * 32;
        __syncthreads();
        for (int l = t; l < 1024; l += 256) {
            int p = l >> 3, kk4 = (l & 7) * 4;
            float4 cv = *(const float4*)&g_cat[((size_t)(b * NPOS + n0 + p)) * DIM + ci0 + kk4];
            float4 wv = *(const float4*)&g_M[(co0 + p) * DIM + ci0 + kk4];
            float* cd = &cs[kk4 * 132 + p];
            cd[0] = cv.x; cd[132] = cv.y; cd[264] = cv.z; cd[396] = cv.w;
            float* wd = &wfs[kk4 * 132 + p];
            wd[0] = wv.x; wd[132] = wv.y; wd[264] = wv.z; wd[396] = wv.w;
        }
        __syncthreads();
        #pragma unroll 4
        for (int kk = 0; kk < 32; ++kk) {
            float4 a0 = *(const float4*)&cs[kk * 132 + tx * 4];
            float4 a1 = *(const float4*)&cs[kk * 132 + 64 + tx * 4];
            float4 w0 = *(const float4*)&wfs[kk * 132 + ty * 4];
            float4 w1 = *(const float4*)&wfs[kk * 132 + 64 + ty * 4];
            float av[8] = {a0.x, a0.y, a0.z, a0.w, a1.x, a1.y, a1.z, a1.w};
            float wv[8] = {w0.x, w0.y, w0.z, w0.w, w1.x, w1.y, w1.z, w1.w};
            #pragma unroll
            for (int j = 0; j < 8; ++j)
                #pragma unroll
                for (int i = 0; i < 8; ++i)
                    acc[j][i] += wv[j] * av[i];
        }
    }

    #pragma unroll
    for (int j = 0; j < 8; ++j) {
        int co = co0 + (j >> 2) * 64 + ty * 4 + (j & 3);
        float cc = g_c0[co];
        float* op = out + ((size_t)(b * DIM + co)) * NPOS + n0;
        float4 v0 = make_float4(acc[j][0] + cc, acc[j][1] + cc, acc[j][2] + cc, acc[j][3] + cc);
        float4 v1 = make_float4(acc[j][4] + cc, acc[j][5] + cc, acc[j][6] + cc, acc[j][7] + cc);
        *(float4*)&op[tx * 4] = v0;
        *(float4*)&op[64 + tx * 4] = v1;
    }
}

// ------------------------- launch -------------------------
extern "C" void kernel_launch(void* const* d_in, const int* in_sizes, int n_in,
                              void* d_out, int out_size) {
    const float* x      = (const float*)d_in[0];
    const float* w3 = (const float*)d_in[1];  const float* b3 = (const float*)d_in[2];
    const float* w5 = (const float*)d_in[3];  const float* b5 = (const float*)d_in[4];
    const float* w7 = (const float*)d_in[5];  const float* b7 = (const float*)d_in[6];
    const float* w9 = (const float*)d_in[7];  const float* b9 = (const float*)d_in[8];
    const float* w_qkv  = (const float*)d_in[9];
    const float* w_proj = (const float*)d_in[10];
    const float* b_proj = (const float*)d_in[11];
    const float* w_fin  = (const float*)d_in[12];
    const float* b_fin  = (const float*)d_in[13];
    const float* sw     = (const float*)d_in[14];
    float* out = (float*)d_out;

    k0_fuse<<<DIM, 256>>>(w_fin, w_proj, b_proj, b_fin, sw);
    k1_dwconv_all<<<dim3(S, BB, 4), 256>>>(x, w3, b3, w5, b5, w7, b7, w9, b9);
    k2_qkv<<<dim3(64, BB, 4), 256>>>(w_qkv);
    k3r_reduce<<<4 * BB * HEADS, 256>>>();
    k4_attn<<<dim3(64, BB, 4), 256>>>();
    k5_final<<<dim3(32, 2, BB), 256>>>(out);
}